// round 16
// baseline (speedup 1.0000x reference)
#include <cuda_runtime.h>
#include <cuda_fp16.h>
#include <cstdint>

#define Bsz 8
#define Cch 64
#define Hh  128
#define Wwi 128
#define Och 64
#define HW  (Hh*Wwi)

#define THREADS 256
#define NBLK    (Bsz*64)        // 512 CTAs, 2 sequential row-tiles each
#define NSUPER  4
#define NPH     9
#define NSTEPS  (NSUPER*NPH)    // 36
#define NCHUNKS 8               // 2 tiles x 4 supers, flat pipelined loop

// smem (floats): two chunk buffers
//   x: 16ch x 3 halo rows, row pitch 136: col3 = gw=-1 (zero), cols 4..131 = gw 0..127,
//      col132 = gw=128 (zero)
//   channel stride XSTR=420 (≡4 mod 16 -> pair-groups hit banks 0/8/16/24; 16B-aligned rows)
//   gc: 16 x 132
#define ROWP    136
#define XSTR    420
#define XGC_OFF (16*XSTR)              // 6720
#define GCSTR   132
#define BUF_FL  (XGC_OFF + 16*GCSTR)   // 8832
#define SMEM_FL (2*BUF_FL)             // 17664 fl = 70656 B

// B fragments: [step=36][j=4][lane=32] x uint4, lane innermost (coalesced)
__device__ uint4 d_bfrag[NSTEPS*4*32];

// ---------------- helpers ----------------
__device__ __forceinline__ uint32_t smem_u32(const void* p) {
    uint32_t a;
    asm("{ .reg .u64 t; cvta.to.shared.u64 t, %1; cvt.u32.u64 %0, t; }"
        : "=r"(a) : "l"(p));
    return a;
}
__device__ __forceinline__ void cp16(uint32_t dst, const void* src, int nbytes) {
    asm volatile("cp.async.cg.shared.global [%0], [%1], 16, %2;"
                 :: "r"(dst), "l"(src), "r"(nbytes));
}
__device__ __forceinline__ void cp_commit() { asm volatile("cp.async.commit_group;"); }
__device__ __forceinline__ void cp_wait1()  { asm volatile("cp.async.wait_group 1;" ::: "memory"); }
__device__ __forceinline__ void cp_wait0()  { asm volatile("cp.async.wait_group 0;" ::: "memory"); }
__device__ __forceinline__ uint32_t packh2(float lo, float hi) {
    __half2 h = __floats2half2_rn(lo, hi);
    return *reinterpret_cast<uint32_t*>(&h);
}
__device__ __forceinline__ uint32_t hadd2(uint32_t a, uint32_t b) {
    uint32_t r; asm("add.f16x2 %0, %1, %2;" : "=r"(r) : "r"(a), "r"(b)); return r;
}
__device__ __forceinline__ uint32_t tanh_h2(uint32_t a) {
    uint32_t r; asm("tanh.approx.f16x2 %0, %1;" : "=r"(r) : "r"(a)); return r;
}
__device__ __forceinline__ uint32_t hfma2(uint32_t a, uint32_t b, uint32_t c) {
    uint32_t r; asm("fma.rn.f16x2 %0, %1, %2, %3;" : "=r"(r) : "r"(a), "r"(b), "r"(c)); return r;
}
__device__ __forceinline__ void hmma(float& c0, float& c1, float& c2, float& c3,
                                     uint32_t a0, uint32_t a1, uint32_t a2, uint32_t a3,
                                     uint32_t b0, uint32_t b1) {
    asm("mma.sync.aligned.m16n8k16.row.col.f32.f16.f16.f32 "
        "{%0,%1,%2,%3}, {%4,%5,%6,%7}, {%8,%9}, {%0,%1,%2,%3};"
        : "+f"(c0), "+f"(c1), "+f"(c2), "+f"(c3)
        : "r"(a0), "r"(a1), "r"(a2), "r"(a3), "r"(b0), "r"(b1));
}

// ---------------- B fragment prep: step (g,p), slot s -> w[o][g*16+s][p] ----
__global__ void prep_bfrag(const float* __restrict__ w) {
    int i = blockIdx.x * blockDim.x + threadIdx.x;   // [step][j][lane]
    if (i < NSTEPS*4*32) {
        int lane = i & 31;
        int j    = (i >> 5) & 3;
        int step = i >> 7;
        int g    = step / NPH;
        int p    = step - g*NPH;
        int kb   = (lane & 3) * 2;
        uint32_t v[4];
        #pragma unroll
        for (int t = 0; t < 2; ++t) {
            int nt = 2*j + t;
            int o  = nt*8 + (lane >> 2);
            float f[4];
            #pragma unroll
            for (int q = 0; q < 4; ++q) {
                int s = kb + (q >> 1)*8 + (q & 1);
                int c = g*16 + s;
                f[q] = w[(o*Cch + c)*9 + p];
            }
            v[2*t]   = packh2(f[0], f[1]);
            v[2*t+1] = packh2(f[2], f[3]);
        }
        uint4 r; r.x = v[0]; r.y = v[1]; r.z = v[2]; r.w = v[3];
        d_bfrag[i] = r;
    }
}

// ---------------- main kernel ----------------
extern __shared__ float sm[];

__global__ void __launch_bounds__(THREADS, 2)
paka_hmma(const float* __restrict__ x,
          const float* __restrict__ gc,
          const float* __restrict__ gsp,
          float* __restrict__ out)
{
    const int tid  = threadIdx.x;
    const int lane = tid & 31;
    const int wid  = tid >> 5;
    const int t    = blockIdx.x;
    const int b    = t >> 6;
    const int hh   = (t & 63) << 1;       // tiles at rows hh, hh+1

    const uint32_t sbase = smem_u32(sm);

    // ---- zero the constant halo columns once (cols 3 and 132, both buffers) ----
    if (tid < 192) {
        int buf = tid / 96;
        int rem = tid - buf*96;
        int cl  = rem / 6;
        int r6  = rem - cl*6;
        int r4  = r6 >> 1;
        int col = (r6 & 1) ? 132 : 3;
        sm[buf*BUF_FL + cl*XSTR + r4*ROWP + col] = 0.f;
    }

    const float* xB  = x  + (size_t)b*Cch*HW;
    const float* gcB = gc + (size_t)b*Cch*HW;

    // stage chunk c (c = tile*4 + super) into buffer c&1
    auto stage_chunk = [&](int c) {
        const int ti = c >> 2;
        const int cg = c & 3;
        const int h  = hh + ti;
        const uint32_t dst0 = sbase + (c & 1)*BUF_FL*4;
        const float* xc = xB + (size_t)cg*16*HW;
        #pragma unroll
        for (int it = 0; it < 6; ++it) {
            int idx = tid + it*THREADS;          // < 1536
            int cl  = idx / 96;
            int rem = idx - cl*96;
            int r4  = rem >> 5;
            int seg = rem & 31;
            int gh  = h - 1 + r4;
            bool inb = ((unsigned)gh < Hh);
            const float* src = inb ? (xc + (size_t)cl*HW + gh*Wwi + seg*4) : xB;
            cp16(dst0 + (uint32_t)(cl*XSTR + r4*ROWP + 4 + seg*4)*4, src, inb ? 16 : 0);
        }
        const float* gcc = gcB + (size_t)cg*16*HW + (size_t)h*Wwi;
        #pragma unroll
        for (int it = 0; it < 2; ++it) {
            int idx = tid + it*THREADS;          // < 512
            int cl  = idx >> 5;
            int seg = idx & 31;
            cp16(dst0 + (uint32_t)(XGC_OFF + cl*GCSTR + seg*4)*4,
                 gcc + (size_t)cl*HW + seg*4, 16);
        }
    };
    stage_chunk(0);
    cp_commit();

    const int r0 = wid*16 + (lane >> 2);
    const int r1 = r0 + 8;
    const int qp = (lane & 3)*2;

    // gs broadcast half2 packs for tile 0 (tile 1 reloaded under tile-0 epilogue)
    const float* gsb = gsp + (size_t)b*9*HW;
    uint32_t gs2a[9], gs2b[9];
    #pragma unroll
    for (int p = 0; p < 9; ++p) {
        float v0 = __ldg(gsb + (size_t)p*HW + (size_t)hh*Wwi + r0);
        float v1 = __ldg(gsb + (size_t)p*HW + (size_t)hh*Wwi + r1);
        gs2a[p] = packh2(v0, v0);
        gs2b[p] = packh2(v1, v1);
    }

    float acc[32];
    #pragma unroll
    for (int i = 0; i < 32; ++i) acc[i] = 0.f;

    for (int c = 0; c < NCHUNKS; ++c) {
        const int g  = c & 3;
        const int ti = c >> 2;
        if (c + 1 < NCHUNKS) { stage_chunk(c + 1); cp_commit(); cp_wait1(); }
        else                 { cp_wait0(); }
        __syncthreads();

        const float* bs = sm + (c & 1)*BUF_FL;
        // per-thread channel base pointers (channels qp, qp+1, qp+8, qp+9)
        const float* p00 = bs + (qp    )*XSTR + r0;
        const float* p01 = bs + (qp    )*XSTR + r1;
        const float* p10 = bs + (qp + 1)*XSTR + r0;
        const float* p11 = bs + (qp + 1)*XSTR + r1;
        const float* p20 = bs + (qp + 8)*XSTR + r0;
        const float* p21 = bs + (qp + 8)*XSTR + r1;
        const float* p30 = bs + (qp + 9)*XSTR + r0;
        const float* p31 = bs + (qp + 9)*XSTR + r1;

        // gc channel-pairs packed to half2, hoisted per super-group
        const float* gp = bs + XGC_OFF;
        const uint32_t gc2_0 = packh2(gp[(qp    )*GCSTR + r0], gp[(qp + 1)*GCSTR + r0]);
        const uint32_t gc2_1 = packh2(gp[(qp    )*GCSTR + r1], gp[(qp + 1)*GCSTR + r1]);
        const uint32_t gc2_2 = packh2(gp[(qp + 8)*GCSTR + r0], gp[(qp + 9)*GCSTR + r0]);
        const uint32_t gc2_3 = packh2(gp[(qp + 8)*GCSTR + r1], gp[(qp + 9)*GCSTR + r1]);

        #pragma unroll
        for (int p = 0; p < NPH; ++p) {
            const int di  = p / 3;
            const int dj  = p - 3*di;
            const int imm = di*ROWP + dj + 3;     // gw = w + dj - 1 at col gw+4

            const uint4* bp = d_bfrag + (size_t)(g*NPH + p)*128 + lane;
            uint4 B0 = bp[0];
            uint4 B1 = bp[32];

            const uint32_t xp0 = packh2(p00[imm], p10[imm]);
            const uint32_t xp1 = packh2(p01[imm], p11[imm]);
            const uint32_t xp2 = packh2(p20[imm], p30[imm]);
            const uint32_t xp3 = packh2(p21[imm], p31[imm]);

            const uint32_t t0 = tanh_h2(hadd2(gc2_0, gs2a[p]));
            const uint32_t t1 = tanh_h2(hadd2(gc2_1, gs2b[p]));
            const uint32_t t2 = tanh_h2(hadd2(gc2_2, gs2a[p]));
            const uint32_t t3 = tanh_h2(hadd2(gc2_3, gs2b[p]));

            const uint32_t a0 = hfma2(xp0, t0, xp0);
            const uint32_t a1 = hfma2(xp1, t1, xp1);
            const uint32_t a2 = hfma2(xp2, t2, xp2);
            const uint32_t a3 = hfma2(xp3, t3, xp3);

            hmma(acc[0],  acc[1],  acc[2],  acc[3],  a0,a1,a2,a3, B0.x, B0.y);
            hmma(acc[4],  acc[5],  acc[6],  acc[7],  a0,a1,a2,a3, B0.z, B0.w);
            hmma(acc[8],  acc[9],  acc[10], acc[11], a0,a1,a2,a3, B1.x, B1.y);
            hmma(acc[12], acc[13], acc[14], acc[15], a0,a1,a2,a3, B1.z, B1.w);

            uint4 B2 = bp[64];
            uint4 B3 = bp[96];
            hmma(acc[16], acc[17], acc[18], acc[19], a0,a1,a2,a3, B2.x, B2.y);
            hmma(acc[20], acc[21], acc[22], acc[23], a0,a1,a2,a3, B2.z, B2.w);
            hmma(acc[24], acc[25], acc[26], acc[27], a0,a1,a2,a3, B3.x, B3.y);
            hmma(acc[28], acc[29], acc[30], acc[31], a0,a1,a2,a3, B3.z, B3.w);
        }

        if (g == 3) {
            // reload gs packs for the next tile first — LDG latency hides under epilogue
            if (ti == 0) {
                #pragma unroll
                for (int p = 0; p < 9; ++p) {
                    float v0 = __ldg(gsb + (size_t)p*HW + (size_t)(hh + 1)*Wwi + r0);
                    float v1 = __ldg(gsb + (size_t)p*HW + (size_t)(hh + 1)*Wwi + r1);
                    gs2a[p] = packh2(v0, v0);
                    gs2b[p] = packh2(v1, v1);
                }
            }
            // epilogue for tile ti
            float* ob = out + ((size_t)b*Och)*HW + (size_t)(hh + ti)*Wwi;
            #pragma unroll
            for (int nt = 0; nt < 8; ++nt) {
                const int o0 = nt*8 + qp;
                float* p = ob + (size_t)o0*HW;
                p[r0]      = acc[nt*4 + 0];
                p[HW + r0] = acc[nt*4 + 1];
                p[r1]      = acc[nt*4 + 2];
                p[HW + r1] = acc[nt*4 + 3];
            }
            #pragma unroll
            for (int i = 0; i < 32; ++i) acc[i] = 0.f;
        }
        __syncthreads();   // all done reading bs before restaging
    }
}

extern "C" void kernel_launch(void* const* d_in, const int* in_sizes, int n_in,
                              void* d_out, int out_size) {
    const float* x  = (const float*)d_in[0];
    const float* gc = (const float*)d_in[1];
    const float* gs = (const float*)d_in[2];
    const float* w  = (const float*)d_in[3];
    float* out = (float*)d_out;

    prep_bfrag<<<(NSTEPS*4*32 + 255)/256, 256>>>(w);

    const int smem_bytes = SMEM_FL * 4;
    (void)cudaFuncSetAttribute(paka_hmma,
                               cudaFuncAttributeMaxDynamicSharedMemorySize,
                               smem_bytes);
    paka_hmma<<<NBLK, THREADS, smem_bytes>>>(x, gc, gs, out);
}